// round 7
// baseline (speedup 1.0000x reference)
#include <cuda_runtime.h>
#include <cuda_bf16.h>

// ProbsToSpan: B=16, S=4096.
//   predicted_start = argmax_s ( start[s] * suffix_max(end)[s] )
//   predicted_end   = argmax_t ( end[t]   * prefix_max(start)[t] )
// (bit-exact vs reference's triu(outer-product) since inputs are >= 0 and
//  fp32 multiply by a non-negative constant is RN-monotone).
//
// Latency-bound kernel: 2 CTAs per batch (job 0 -> predicted_start,
// job 1 -> predicted_end) so each CTA runs a single scan+argmax chain.
// All reductions use u32 ordered-int compares (valid for non-negative fp32)
// and REDUX.SYNC where possible to shorten the dependency chain.

#define SLEN 4096
#define TPB  256
#define NW   (TPB / 32)           // 8 warps
#define CHUNK (SLEN / TPB)        // 16 contiguous elements per thread

__global__ __launch_bounds__(TPB, 1)
void ProbsToSpan_49143015801170_kernel(const float* __restrict__ start_p,
                                       const float* __restrict__ end_p,
                                       float* __restrict__ out, int B) {
    const int job  = blockIdx.x & 1;    // 0: predicted_start, 1: predicted_end
    const int b    = blockIdx.x >> 1;
    const int tid  = threadIdx.x;
    const int lane = tid & 31;
    const int wid  = tid >> 5;
    const int base = tid * CHUNK;       // 64B-aligned element offset

    const float* sp = start_p + (size_t)b * SLEN;
    const float* ep = end_p   + (size_t)b * SLEN;
    // A = array whose running max we scan; M = array we multiply by.
    // job 0: suffix_max over end, multiply start.
    // job 1: prefix_max over start, multiply end.
    const float* A = job ? sp : ep;
    const float* M = job ? ep : sp;

    // Front-batched float4 loads (8 independent LDG.128 per thread).
    float a[CHUNK], m[CHUNK];
    const float4* A4 = (const float4*)(A + base);
    const float4* M4 = (const float4*)(M + base);
#pragma unroll
    for (int i = 0; i < CHUNK / 4; i++) {
        float4 x = A4[i];
        float4 y = M4[i];
        a[4*i+0] = x.x; a[4*i+1] = x.y; a[4*i+2] = x.z; a[4*i+3] = x.w;
        m[4*i+0] = y.x; m[4*i+1] = y.y; m[4*i+2] = y.z; m[4*i+3] = y.w;
    }

    // Per-chunk max of A (inputs in [0,1): 0.0f identity).
    float amax = 0.f;
#pragma unroll
    for (int i = 0; i < CHUNK; i++) amax = fmaxf(amax, a[i]);

    __shared__ float wtot[NW];
    __shared__ unsigned wval[NW];
    __shared__ int     widx[NW];

    float excl;   // exclusive running max of A outside this thread's chunk
    if (job) {
        // PREFIX direction (ascending lanes).
        float incl = amax;
#pragma unroll
        for (int off = 1; off < 32; off <<= 1) {
            float o = __shfl_up_sync(0xffffffffu, incl, off);
            if (lane >= off) incl = fmaxf(incl, o);
        }
        float e = __shfl_up_sync(0xffffffffu, incl, 1);
        if (lane == 0) e = 0.f;
        if (lane == 31) wtot[wid] = incl;     // warp total
        __syncthreads();
        float wprev = 0.f;
        for (int w = 0; w < wid; w++) wprev = fmaxf(wprev, wtot[w]);
        excl = fmaxf(e, wprev);
    } else {
        // SUFFIX direction (descending lanes).
        float incl = amax;
#pragma unroll
        for (int off = 1; off < 32; off <<= 1) {
            float o = __shfl_down_sync(0xffffffffu, incl, off);
            if (lane < 32 - off) incl = fmaxf(incl, o);
        }
        float e = __shfl_down_sync(0xffffffffu, incl, 1);
        if (lane == 31) e = 0.f;
        if (lane == 0) wtot[wid] = incl;      // warp total
        __syncthreads();
        float wnext = 0.f;
        for (int w = wid + 1; w < NW; w++) wnext = fmaxf(wnext, wtot[w]);
        excl = fmaxf(e, wnext);
    }

    // Product + per-thread argmax. Non-negative fp32 -> uint compare is exact.
    unsigned bestv = 0u;
    int      besti = base;
    float run = excl;
    if (job) {
        // ascending scan, strict '>' keeps smallest index on ties
#pragma unroll
        for (int i = 0; i < CHUNK; i++) {
            run = fmaxf(run, a[i]);
            unsigned v = __float_as_uint(m[i] * run);
            if (v > bestv) { bestv = v; besti = base + i; }
        }
    } else {
        // descending scan, '>=' keeps smallest index winning
#pragma unroll
        for (int i = CHUNK - 1; i >= 0; i--) {
            run = fmaxf(run, a[i]);
            unsigned v = __float_as_uint(m[i] * run);
            if (v >= bestv) { bestv = v; besti = base + i; }
        }
    }

    // Warp argmax via REDUX: max value, then min index among value-matches.
    unsigned vmax = __reduce_max_sync(0xffffffffu, bestv);
    int cand = (bestv == vmax) ? besti : 0x7fffffff;
    int imin = __reduce_min_sync(0xffffffffu, cand);

    if (lane == 0) { wval[wid] = vmax; widx[wid] = imin; }
    __syncthreads();

    // Final cross-warp argmax in warp 0.
    if (wid == 0) {
        unsigned v = (lane < NW) ? wval[lane] : 0u;
        int      i = (lane < NW) ? widx[lane] : 0x7fffffff;
        unsigned fv = __reduce_max_sync(0xffffffffu, v);
        int fc = (v == fv) ? i : 0x7fffffff;
        int fi = __reduce_min_sync(0xffffffffu, fc);
        if (lane == 0) out[job * B + b] = (float)fi;
    }
}

extern "C" void kernel_launch(void* const* d_in, const int* in_sizes, int n_in,
                              void* d_out, int out_size) {
    const float* start_p = (const float*)d_in[0];
    const float* end_p   = (const float*)d_in[1];
    float* out = (float*)d_out;
    int B = in_sizes[0] / SLEN;   // 16
    ProbsToSpan_49143015801170_kernel<<<2 * B, TPB>>>(start_p, end_p, out, B);
}

// round 8
// speedup vs baseline: 1.0435x; 1.0435x over previous
#include <cuda_runtime.h>
#include <cuda_bf16.h>

// ProbsToSpan: B=16, S=4096.
//   predicted_start = argmax_s ( start[s] * suffix_max(end)[s] )
//   predicted_end   = argmax_t ( end[t]   * prefix_max(start)[t] )
// Bit-exact vs reference's triu(outer-product): inputs >= 0 and fp32 multiply
// by a non-negative constant is RN-monotone.
//
// Latency-chain-optimized: 2 CTAs per batch (job 0 -> predicted_start,
// job 1 -> predicted_end). Per-thread scan and argmax are log-depth trees
// instead of serial loops; reductions use REDUX.SYNC on u32 ordered compares
// (exact for non-negative fp32).

#define SLEN 4096
#define TPB  256
#define NW   (TPB / 32)           // 8 warps
#define CHUNK (SLEN / TPB)        // 16 contiguous elements per thread

__global__ __launch_bounds__(TPB, 1)
void ProbsToSpan_49143015801170_kernel(const float* __restrict__ start_p,
                                       const float* __restrict__ end_p,
                                       float* __restrict__ out, int B) {
    const int job  = blockIdx.x & 1;    // 0: predicted_start, 1: predicted_end
    const int b    = blockIdx.x >> 1;
    const int tid  = threadIdx.x;
    const int lane = tid & 31;
    const int wid  = tid >> 5;
    const int base = tid * CHUNK;       // 64B-aligned element offset

    const float* sp = start_p + (size_t)b * SLEN;
    const float* ep = end_p   + (size_t)b * SLEN;
    // A = array whose running max we scan; M = array we multiply by.
    // job 0: suffix_max over end, multiply start.
    // job 1: prefix_max over start, multiply end.
    const float* A = job ? sp : ep;
    const float* M = job ? ep : sp;

    // Front-batched float4 loads (8 independent LDG.128 per thread).
    float a[CHUNK], m[CHUNK];
    const float4* A4 = (const float4*)(A + base);
    const float4* M4 = (const float4*)(M + base);
#pragma unroll
    for (int i = 0; i < CHUNK / 4; i++) {
        float4 x = A4[i];
        float4 y = M4[i];
        a[4*i+0] = x.x; a[4*i+1] = x.y; a[4*i+2] = x.z; a[4*i+3] = x.w;
        m[4*i+0] = y.x; m[4*i+1] = y.y; m[4*i+2] = y.z; m[4*i+3] = y.w;
    }

    // In-register log-tree scan of A: after this, a[i] holds the inclusive
    // prefix max (job 1) or inclusive suffix max (job 0) within the chunk.
    // Depth log2(CHUNK)=4; each round's ops are independent (not a serial chain).
    float amax;
    if (job) {
#pragma unroll
        for (int off = 1; off < CHUNK; off <<= 1)
#pragma unroll
            for (int i = CHUNK - 1; i >= off; i--) a[i] = fmaxf(a[i], a[i - off]);
        amax = a[CHUNK - 1];
    } else {
#pragma unroll
        for (int off = 1; off < CHUNK; off <<= 1)
#pragma unroll
            for (int i = 0; i < CHUNK - off; i++) a[i] = fmaxf(a[i], a[i + off]);
        amax = a[0];
    }

    __shared__ float    wtot[NW];
    __shared__ unsigned wval[NW];
    __shared__ int      widx[NW];

    float excl;   // max of A over all elements outside this thread's chunk,
                  // on the scan side (left for prefix / right for suffix).
    if (job) {
        // PREFIX direction (ascending lanes).
        float incl = amax;
#pragma unroll
        for (int off = 1; off < 32; off <<= 1) {
            float o = __shfl_up_sync(0xffffffffu, incl, off);
            if (lane >= off) incl = fmaxf(incl, o);
        }
        float e = __shfl_up_sync(0xffffffffu, incl, 1);
        if (lane == 0) e = 0.f;             // inputs in [0,1): 0 identity
        if (lane == 31) wtot[wid] = incl;   // warp total
        __syncthreads();
        float wprev = 0.f;
        for (int w = 0; w < wid; w++) wprev = fmaxf(wprev, wtot[w]);
        excl = fmaxf(e, wprev);
    } else {
        // SUFFIX direction (descending lanes).
        float incl = amax;
#pragma unroll
        for (int off = 1; off < 32; off <<= 1) {
            float o = __shfl_down_sync(0xffffffffu, incl, off);
            if (lane < 32 - off) incl = fmaxf(incl, o);
        }
        float e = __shfl_down_sync(0xffffffffu, incl, 1);
        if (lane == 31) e = 0.f;
        if (lane == 0) wtot[wid] = incl;    // warp total
        __syncthreads();
        float wnext = 0.f;
        for (int w = wid + 1; w < NW; w++) wnext = fmaxf(wnext, wtot[w]);
        excl = fmaxf(e, wnext);
    }

    // Products: all CHUNK values independent (running max is precomputed).
    // Non-negative fp32 -> u32 compare is order-exact.
    unsigned bv[CHUNK];
    int      bi[CHUNK];
#pragma unroll
    for (int i = 0; i < CHUNK; i++) {
        bv[i] = __float_as_uint(m[i] * fmaxf(excl, a[i]));
        bi[i] = base + i;
    }
    // Pairwise tournament argmax, depth 4. Ties keep the lower half, i.e. the
    // smaller index -> jnp.argmax first-index semantics.
#pragma unroll
    for (int s = CHUNK >> 1; s >= 1; s >>= 1)
#pragma unroll
        for (int i = 0; i < s; i++)
            if (bv[i + s] > bv[i]) { bv[i] = bv[i + s]; bi[i] = bi[i + s]; }
    unsigned bestv = bv[0];
    int      besti = bi[0];

    // Warp argmax via REDUX: max value, then min index among value-matches.
    unsigned vmax = __reduce_max_sync(0xffffffffu, bestv);
    int cand = (bestv == vmax) ? besti : 0x7fffffff;
    int imin = __reduce_min_sync(0xffffffffu, cand);

    if (lane == 0) { wval[wid] = vmax; widx[wid] = imin; }
    __syncthreads();

    // Final cross-warp argmax in warp 0.
    if (wid == 0) {
        unsigned v = (lane < NW) ? wval[lane] : 0u;
        int      i = (lane < NW) ? widx[lane] : 0x7fffffff;
        unsigned fv = __reduce_max_sync(0xffffffffu, v);
        int fc = (v == fv) ? i : 0x7fffffff;
        int fi = __reduce_min_sync(0xffffffffu, fc);
        if (lane == 0) out[job * B + b] = (float)fi;
    }
}

extern "C" void kernel_launch(void* const* d_in, const int* in_sizes, int n_in,
                              void* d_out, int out_size) {
    const float* start_p = (const float*)d_in[0];
    const float* end_p   = (const float*)d_in[1];
    float* out = (float*)d_out;
    int B = in_sizes[0] / SLEN;   // 16
    ProbsToSpan_49143015801170_kernel<<<2 * B, TPB>>>(start_p, end_p, out, B);
}